// round 16
// baseline (speedup 1.0000x reference)
#include <cuda_runtime.h>
#include <math.h>

#define BB   32
#define LL   1024
#define DG   1024
#define HH   1024
#define OUTW 2048
#define BL   (BB * LL)          // 32768 rows

// Split-K partials, packed per row: g_part4[bl] = {hq0, hq1, hq2, hq3}
__device__ float4 g_part4[BL];

// ---------------------------------------------------------------------------
// Gate partials: split-K-4 GEMM (R14/R15 proven form) + EXPLICIT PDL trigger
// placed AFTER the partial stores. Secondary's cudaGridDependencySynchronize
// releases once all CTAs have stored+triggered — skips kernel teardown drain.
// Grid 512 = (32 lt) x (4 bg) x (4 hq), 512 threads. MLP=16 W loads.
// ---------------------------------------------------------------------------
__global__ __launch_bounds__(512, 2)
void gate_partial(const float* __restrict__ query,
                  const float* __restrict__ W)
{
    __shared__ float sq[8 * 256];         // 8 KiB query slice
    __shared__ float red[16][8][32];      // 16 KiB

    const int tid  = threadIdx.x;
    const int warp = tid >> 5;
    const int lane = tid & 31;
    const int bid  = blockIdx.x;
    const int lt   = bid & 31;            // l-tile
    const int bg   = (bid >> 5) & 3;      // batch group
    const int hq   = bid >> 7;            // h-quarter

    {
        const int b = tid >> 6;
        const int j = tid & 63;
        ((float4*)sq)[b * 64 + j] =
            __ldg((const float4*)query + (bg * 8 + b) * (HH / 4) + hq * 64 + j);
    }
    __syncthreads();

    const int l  = lt * 32 + lane;
    const int h0 = hq * 256 + warp * 16;

    float w[16];
    #pragma unroll
    for (int j = 0; j < 16; ++j)
        w[j] = __ldg(&W[(h0 + j) * LL + l]);

    float acc[8];
    #pragma unroll
    for (int b = 0; b < 8; ++b) acc[b] = 0.f;

    #pragma unroll
    for (int b = 0; b < 8; ++b) {
        const float* qb = sq + b * 256 + warp * 16;
        #pragma unroll
        for (int j = 0; j < 16; ++j)
            acc[b] = fmaf(qb[j], w[j], acc[b]);
    }

    #pragma unroll
    for (int b = 0; b < 8; ++b) red[warp][b][lane] = acc[b];
    __syncthreads();

    if (tid < 256) {
        const int b = tid >> 5;
        float s = 0.f;
        #pragma unroll
        for (int w2 = 0; w2 < 16; ++w2) s += red[w2][b][lane];
        ((float*)&g_part4[(bg * 8 + b) * LL + l])[hq] = s;
    }

    // Order all CTA stores, then signal dependents. Writes before the trigger
    // are visible to the secondary after cudaGridDependencySynchronize().
    __syncthreads();
    if (tid == 0) {
        __threadfence();
        cudaTriggerProgrammaticLaunchCompletion();
    }
}

// ---------------------------------------------------------------------------
// Stream: R15's proven form (pristine R2 + barrier-free redundant finalize),
// PDL secondary. Grid-dependency sync AFTER the gate-independent loads.
// ---------------------------------------------------------------------------
__global__ __launch_bounds__(256, 8)
void stream_kernel(const float4* __restrict__ graph,
                   const float4* __restrict__ query,
                   const float*  __restrict__ bias,
                   float4* __restrict__ out)
{
    const int bl  = blockIdx.x;           // b*LL + l
    const int b   = bl >> 10;
    const int l   = bl & 1023;
    const int tid = threadIdx.x;

    // Gate-independent long-latency loads first
    const float4 v = __ldcs(&graph[(long long)bl * (DG / 4) + tid]);
    const float4 q = __ldg(&query[b * (HH / 4) + tid]);
    const float  bi = __ldg(&bias[l]);    // warp-broadcast

    // Wait until all gate CTAs have stored + triggered
    cudaGridDependencySynchronize();

    const float4 p = __ldcg(&g_part4[bl]); // warp-broadcast, 1 sector
    const float s = bi + ((p.x + p.y) + (p.z + p.w));
    const float g = 1.0f / (1.0f + __expf(-s));

    float4* o = out + (long long)bl * (OUTW / 4);
    __stcs(&o[tid],            make_float4(v.x * g, v.y * g, v.z * g, v.w * g));
    __stcs(&o[(DG / 4) + tid], q);
}

extern "C" void kernel_launch(void* const* d_in, const int* in_sizes, int n_in,
                              void* d_out, int out_size)
{
    const float* graph = (const float*)d_in[0];
    const float* query = (const float*)d_in[1];
    const float* W     = (const float*)d_in[2];
    const float* bias  = (const float*)d_in[3];
    float* out = (float*)d_out;

    gate_partial<<<512, 512>>>(query, W);

    cudaLaunchConfig_t cfg = {};
    cfg.gridDim  = dim3(BL, 1, 1);
    cfg.blockDim = dim3(256, 1, 1);
    cfg.dynamicSmemBytes = 0;
    cfg.stream = 0;
    cudaLaunchAttribute attr[1];
    attr[0].id = cudaLaunchAttributeProgrammaticStreamSerialization;
    attr[0].val.programmaticStreamSerializationAllowed = 1;
    cfg.attrs = attr;
    cfg.numAttrs = 1;

    cudaLaunchKernelEx(&cfg, stream_kernel,
                       (const float4*)graph, (const float4*)query,
                       bias, (float4*)out);

    (void)in_sizes; (void)n_in; (void)out_size;
}